// round 10
// baseline (speedup 1.0000x reference)
#include <cuda_runtime.h>
#include <math.h>

#define T_MAX 2000
#define B_N   64
#define A_N   32
#define L_N   200

#define NTHREADS 128
#define NWARPS   4
#define PF       8          // steps per group (LDG burst / counter cadence)
#define RING_SZ  2016       // >= T_MAX + PF + 1

__device__ float    d_per_batch[B_N];
__device__ unsigned g_ticket = 0;

__device__ __forceinline__ float ex2(float x) {
    float r; asm("ex2.approx.ftz.f32 %0, %1;" : "=f"(r) : "f"(x)); return r;
}
__device__ __forceinline__ float lg2(float x) {
    float r; asm("lg2.approx.ftz.f32 %0, %1;" : "=f"(r) : "f"(x)); return r;
}
__device__ __forceinline__ float lse2_2(float x, float y) {
    float h = fmaxf(x, y), l = fminf(x, y);
    return h + lg2(1.0f + ex2(l - h));
}
__device__ __forceinline__ float lse2_3(float x, float y, float z) {
    float h = fmaxf(x, y), l = fminf(x, y);
    float m = fmaxf(h, z), s = fminf(h, z);
    return m + lg2(1.0f + ex2(s - m) + ex2(l - m));
}

__device__ __forceinline__ void st_release_shared(unsigned addr, int v) {
    asm volatile("st.release.cta.shared.b32 [%0], %1;" :: "r"(addr), "r"(v) : "memory");
}
__device__ __forceinline__ int ld_acquire_shared(unsigned addr) {
    int v;
    asm volatile("ld.acquire.cta.shared.b32 %0, [%1];" : "=r"(v) : "r"(addr) : "memory");
    return v;
}

__global__ __launch_bounds__(NTHREADS, 1)
void ctc_alpha_kernel(const float* __restrict__ pred,      // (T,B,A) log-softmax (ln)
                      const int*   __restrict__ target,    // (B,L)
                      const int*   __restrict__ pred_lens,
                      const int*   __restrict__ target_lens,
                      float*       __restrict__ out)
{
    const int b    = blockIdx.x;
    const int tid  = threadIdx.x;
    const int wid  = tid >> 5;
    const int lane = tid & 31;

    // ring[w][t] = warp w's lane31 b1 AFTER step t (slot 0 = initial value)
    __shared__ __align__(16) float ring[NWARPS - 1][RING_SZ];
    __shared__ int   cnt[NWARPS - 1];    // release/acquire progress counters
    __shared__ float fin[2];

    const float LOG2E   = 1.4426950408889634f;
    const float LN2     = 0.6931471805599453f;
    const float NEG_BIG = -1e30f;
    const float L2_EPS  = -13.287712379549449f;  // log2(0.0001)
    const float L2_HALF = -1.0028901240599430f;  // log2(0.499)

    const int Tb   = pred_lens[b];
    const int TbM1 = Tb - 1;
    const int tl   = target_lens[b];

    // Final-state owners: f0 = alpha[2tl-1] (odd), f1 = alpha[2tl] (even)
    const int  s0 = 2 * tl - 1, s1 = 2 * tl;
    const bool f0_here = (tid == (s0 >> 2));
    const bool f0_isB  = ((s0 >> 1) & 1) != 0;
    const bool f1_here = (tid == (s1 >> 2));
    const bool f1_isB  = ((s1 >> 1) & 1) != 0;

    // Symbols for the two odd states this thread owns
    int symA = 0, symB = 0;
    if (tid < L_N / 2) {
        int2 sv = ((const int2*)(target + b * L_N))[tid];
        symA = sv.x; symB = sv.y;
    }

    const size_t stride_t = (size_t)B_N * A_N;
    const float* __restrict__ pred_b = pred + (size_t)b * A_N;

    // Init rings/counters (re-run on every graph replay)
    if (tid < NWARPS - 1) { cnt[tid] = 0; ring[tid][0] = L2_EPS; }
    __syncthreads();

    // Register alphas (log2): pair A = (4t,4t+1), pair B = (4t+2,4t+3)
    float a0 = (tid == 0) ? L2_HALF : L2_EPS;
    float a1 = (tid == 0) ? L2_HALF : L2_EPS;
    float b0 = L2_EPS;
    float b1 = L2_EPS;
    float f0c = L2_EPS, f1c = L2_EPS;

    // Per-warp private e-row prefetch: lane l holds column l of each row.
    float ecur[PF], enxt[PF];
    #pragma unroll
    for (int u = 0; u < PF; ++u)
        ecur[u] = pred_b[(size_t)min(1 + u, T_MAX - 1) * stride_t + lane] * LOG2E;
    #pragma unroll
    for (int u = 0; u < PF; ++u)
        enxt[u] = pred_b[(size_t)min(1 + PF + u, T_MAX - 1) * stride_t + lane];

    const unsigned cnt_up   = (wid > 0) ?
        (unsigned)__cvta_generic_to_shared(&cnt[wid - 1]) : 0u;
    const unsigned cnt_self = (wid < NWARPS - 1) ?
        (unsigned)__cvta_generic_to_shared(&cnt[wid]) : 0u;

    for (int base = 1; base < Tb; base += PF) {
        // --- acquire upstream boundary values for this group (slots base-1..base+6) ---
        float rv[PF];
        #pragma unroll
        for (int u = 0; u < PF; ++u) rv[u] = NEG_BIG;
        if (wid > 0) {
            if (lane == 0) {
                const int need = base + PF - 2;
                while (ld_acquire_shared(cnt_up) < need) { }
            }
            __syncwarp();
            if (lane == 0) {
                const float4* rp = (const float4*)(&ring[wid - 1][base - 1]); // 32B aligned
                float4 q0 = rp[0], q1 = rp[1];
                rv[0] = q0.x; rv[1] = q0.y; rv[2] = q0.z; rv[3] = q0.w;
                rv[4] = q1.x; rv[5] = q1.y; rv[6] = q1.z; rv[7] = q1.w;
            }
        }

        #pragma unroll
        for (int u = 0; u < PF; ++u) {
            const int t = base + u;
            const float e = ecur[u];
            const float eb  = __shfl_sync(0xffffffffu, e, 0);
            const float esA = __shfl_sync(0xffffffffu, e, symA);
            const float esB = __shfl_sync(0xffffffffu, e, symB);

            float ap = __shfl_up_sync(0xffffffffu, b1, 1);
            if (lane == 0) ap = rv[u];            // wid 0: rv = NEG_BIG

            float na0 = eb  + lse2_2(a0, ap);
            float na1 = esA + lse2_3(a0, ap, a1);
            float nb0 = eb  + lse2_2(b0, a1);
            float nb1 = esB + lse2_3(b0, a1, b1);
            a0 = na0; a1 = na1; b0 = nb0; b1 = nb1;

            if (wid < NWARPS - 1 && lane == 31) ring[wid][t] = b1;

            if (t == TbM1) {
                if (f0_here) f0c = f0_isB ? b1 : a1;
                if (f1_here) f1c = f1_isB ? b0 : a0;
            }
        }

        // publish this group's boundary trace
        if (wid < NWARPS - 1 && lane == 31)
            st_release_shared(cnt_self, base + PF - 1);

        // rotate e-row registers, issue next group's LDGs
        #pragma unroll
        for (int u = 0; u < PF; ++u) ecur[u] = enxt[u] * LOG2E;
        #pragma unroll
        for (int u = 0; u < PF; ++u)
            enxt[u] = pred_b[(size_t)min(base + 2 * PF + u, T_MAX - 1) * stride_t + lane];
    }

    if (f0_here) fin[0] = f0c;
    if (f1_here) fin[1] = f1c;
    __syncthreads();

    if (tid == 0) {
        d_per_batch[b] = LN2 * lse2_2(fin[0], fin[1]);
        __threadfence();
        unsigned old = atomicAdd(&g_ticket, 1u);
        if (old == B_N - 1) {
            float s = 0.0f;
            #pragma unroll 4
            for (int i = 0; i < B_N; ++i)
                s += __ldcg(&d_per_batch[i]);   // fixed order -> deterministic
            out[0] = -s * (1.0f / (float)B_N);
            g_ticket = 0;                       // reset for next graph replay
        }
    }
}

extern "C" void kernel_launch(void* const* d_in, const int* in_sizes, int n_in,
                              void* d_out, int out_size)
{
    const float* prediction  = (const float*)d_in[0];
    const int*   target      = (const int*)  d_in[1];
    const int*   pred_lens   = (const int*)  d_in[2];
    const int*   target_lens = (const int*)  d_in[3];

    ctc_alpha_kernel<<<B_N, NTHREADS>>>(prediction, target, pred_lens, target_lens,
                                        (float*)d_out);
}

// round 13
// speedup vs baseline: 1.0330x; 1.0330x over previous
#include <cuda_runtime.h>
#include <math.h>

#define T_MAX 2000
#define B_N   64
#define A_N   32
#define L_N   200

#define NTHREADS 128
#define NWARPS   4
#define PF       8          // steps per group
#define RING_SZ  2016       // >= T_MAX + PF, multiple of 8

__device__ float    d_per_batch[B_N];
__device__ unsigned g_ticket = 0;

__device__ __forceinline__ float ex2(float x) {
    float r; asm("ex2.approx.ftz.f32 %0, %1;" : "=f"(r) : "f"(x)); return r;
}
__device__ __forceinline__ float lg2(float x) {
    float r; asm("lg2.approx.ftz.f32 %0, %1;" : "=f"(r) : "f"(x)); return r;
}
__device__ __forceinline__ float lse2_2(float x, float y) {
    float h = fmaxf(x, y), l = fminf(x, y);
    return h + lg2(1.0f + ex2(l - h));
}
__device__ __forceinline__ float lse2_3(float x, float y, float z) {
    float h = fmaxf(x, y), l = fminf(x, y);
    float m = fmaxf(h, z), s = fminf(h, z);
    return m + lg2(1.0f + ex2(s - m) + ex2(l - m));
}
__device__ __forceinline__ void st_release_shared(unsigned addr, int v) {
    asm volatile("st.release.cta.shared.b32 [%0], %1;" :: "r"(addr), "r"(v) : "memory");
}
__device__ __forceinline__ int ld_acquire_shared(unsigned addr) {
    int v;
    asm volatile("ld.acquire.cta.shared.b32 %0, [%1];" : "=r"(v) : "r"(addr) : "memory");
    return v;
}

__global__ __launch_bounds__(NTHREADS, 1)
void ctc_alpha_kernel(const float* __restrict__ pred,      // (T,B,A) log-softmax (ln)
                      const int*   __restrict__ target,    // (B,L)
                      const int*   __restrict__ pred_lens,
                      const int*   __restrict__ target_lens,
                      float*       __restrict__ out)
{
    const int b    = blockIdx.x;
    const int tid  = threadIdx.x;
    const int wid  = tid >> 5;
    const int lane = tid & 31;

    // ring[w][t] = warp w's lane31 b1 AFTER step t (slot 0 = t=0 initial)
    __shared__ __align__(16) float ring[NWARPS - 1][RING_SZ];
    __shared__ int   cnt[NWARPS - 1];               // last completed step, per warp
    __shared__ float rowbuf[NWARPS][2][PF * A_N];   // warp-PRIVATE e-rows, log2
    __shared__ float fin[2];

    const float LOG2E   = 1.4426950408889634f;
    const float LN2     = 0.6931471805599453f;
    const float NEG_BIG = -1e30f;
    const float L2_EPS  = -13.287712379549449f;  // log2(0.0001)
    const float L2_HALF = -1.0028901240599430f;  // log2(0.499)

    const int Tb   = pred_lens[b];
    const int TbM1 = Tb - 1;
    const int tl   = target_lens[b];

    // Final-state owners: f0 = alpha[2tl-1] (odd), f1 = alpha[2tl] (even)
    const int  s0 = 2 * tl - 1, s1 = 2 * tl;
    const bool f0_here = (tid == (s0 >> 2));
    const bool f0_isB  = ((s0 >> 1) & 1) != 0;
    const bool f1_here = (tid == (s1 >> 2));
    const bool f1_isB  = ((s1 >> 1) & 1) != 0;

    int symA = 0, symB = 0;
    if (tid < L_N / 2) {
        int2 sv = ((const int2*)(target + b * L_N))[tid];
        symA = sv.x; symB = sv.y;
    }

    const size_t stride_t = (size_t)B_N * A_N;
    const float* __restrict__ pred_b = pred + (size_t)b * A_N;

    // Reset counters/ring head on every launch (graph replay safe)
    if (tid < NWARPS - 1) { cnt[tid] = 0; ring[tid][0] = L2_EPS; }
    __syncthreads();

    // Register alphas (log2): pair A = (4t,4t+1), pair B = (4t+2,4t+3)
    float a0 = (tid == 0) ? L2_HALF : L2_EPS;
    float a1 = (tid == 0) ? L2_HALF : L2_EPS;
    float b0 = L2_EPS;
    float b1 = L2_EPS;
    float f0c = L2_EPS, f1c = L2_EPS;

    // Warp-private e-row fill: group 0 (rows 1..8) into rowbuf; group 1 into regs
    float* __restrict__ myrows0 = &rowbuf[wid][0][0];
    float* __restrict__ myrows1 = &rowbuf[wid][1][0];
    #pragma unroll
    for (int u = 0; u < PF; ++u)
        myrows0[u * A_N + lane] =
            pred_b[(size_t)min(1 + u, T_MAX - 1) * stride_t + lane] * LOG2E;
    float pf[PF];
    #pragma unroll
    for (int u = 0; u < PF; ++u)
        pf[u] = pred_b[(size_t)min(1 + PF + u, T_MAX - 1) * stride_t + lane];
    __syncwarp();

    const unsigned cnt_up   = (wid > 0) ?
        (unsigned)__cvta_generic_to_shared(&cnt[wid - 1]) : 0u;
    const unsigned cnt_self = (wid < NWARPS - 1) ?
        (unsigned)__cvta_generic_to_shared(&cnt[wid]) : 0u;

    int phase = 0;
    for (int base = 1; base < Tb; base += PF) {
        // ---- acquire upstream boundary trace for steps base-1 .. base+6 ----
        float rv[PF];
        #pragma unroll
        for (int u = 0; u < PF; ++u) rv[u] = NEG_BIG;
        if (wid > 0) {
            if (lane == 0) {
                const int need = base + PF - 2;
                while (ld_acquire_shared(cnt_up) < need) { }
            }
            __syncwarp();
            if (lane == 0) {
                const float4* rp = (const float4*)(&ring[wid - 1][base - 1]); // 32B aligned
                float4 q0 = rp[0], q1 = rp[1];
                rv[0] = q0.x; rv[1] = q0.y; rv[2] = q0.z; rv[3] = q0.w;
                rv[4] = q1.x; rv[5] = q1.y; rv[6] = q1.z; rv[7] = q1.w;
            }
        }

        const float* __restrict__ rcg = phase ? myrows1 : myrows0;
        #pragma unroll
        for (int u = 0; u < PF; ++u) {
            const int t = base + u;
            const float* __restrict__ rc = rcg + u * A_N;
            const float eb  = rc[0];            // LDS broadcast (warp-private buf)
            const float esA = rc[symA];         // conflict-free gather
            const float esB = rc[symB];

            float sh = __shfl_up_sync(0xffffffffu, b1, 1);
            float ap = (lane == 0) ? rv[u] : sh;   // wid 0 lane 0: NEG_BIG

            float na0 = eb  + lse2_2(a0, ap);
            float na1 = esA + lse2_3(a0, ap, a1);
            float nb0 = eb  + lse2_2(b0, a1);
            float nb1 = esB + lse2_3(b0, a1, b1);
            a0 = na0; a1 = na1; b0 = nb0; b1 = nb1;

            if (wid < NWARPS - 1 && lane == 31) ring[wid][t] = b1;

            if (t == TbM1) {
                if (f0_here) f0c = f0_isB ? b1 : a1;
                if (f1_here) f1c = f1_isB ? b0 : a0;
            }
        }

        // publish this group's boundary trace (release orders the ring stores)
        if (wid < NWARPS - 1 && lane == 31)
            st_release_shared(cnt_self, base + PF - 1);

        // commit next group's e-rows (held in regs ~1 group -> DRAM hidden), refill
        float* __restrict__ dst = phase ? myrows0 : myrows1;
        #pragma unroll
        for (int u = 0; u < PF; ++u)
            dst[u * A_N + lane] = pf[u] * LOG2E;
        __syncwarp();
        #pragma unroll
        for (int u = 0; u < PF; ++u)
            pf[u] = pred_b[(size_t)min(base + 2 * PF + u, T_MAX - 1) * stride_t + lane];
        phase ^= 1;
    }

    if (f0_here) fin[0] = f0c;
    if (f1_here) fin[1] = f1c;
    __syncthreads();

    if (tid == 0) {
        d_per_batch[b] = LN2 * lse2_2(fin[0], fin[1]);
        __threadfence();
        unsigned old = atomicAdd(&g_ticket, 1u);
        if (old == B_N - 1) {
            float s = 0.0f;
            #pragma unroll 4
            for (int i = 0; i < B_N; ++i)
                s += __ldcg(&d_per_batch[i]);   // fixed order -> deterministic
            out[0] = -s * (1.0f / (float)B_N);
            g_ticket = 0;                       // reset for next graph replay
        }
    }
}

extern "C" void kernel_launch(void* const* d_in, const int* in_sizes, int n_in,
                              void* d_out, int out_size)
{
    const float* prediction  = (const float*)d_in[0];
    const int*   target      = (const int*)  d_in[1];
    const int*   pred_lens   = (const int*)  d_in[2];
    const int*   target_lens = (const int*)  d_in[3];

    ctc_alpha_kernel<<<B_N, NTHREADS>>>(prediction, target, pred_lens, target_lens,
                                        (float*)d_out);
}

// round 14
// speedup vs baseline: 1.1630x; 1.1258x over previous
#include <cuda_runtime.h>
#include <math.h>

#define T_MAX 2000
#define B_N   64
#define A_N   32
#define L_N   200

#define NTHREADS 128
#define NWARPS   4
#define PF       8         // prefetch group depth == unroll factor

__device__ float    d_per_batch[B_N];
__device__ unsigned g_ticket = 0;

__device__ __forceinline__ float ex2(float x) {
    float r; asm("ex2.approx.ftz.f32 %0, %1;" : "=f"(r) : "f"(x)); return r;
}
__device__ __forceinline__ float lg2(float x) {
    float r; asm("lg2.approx.ftz.f32 %0, %1;" : "=f"(r) : "f"(x)); return r;
}
__device__ __forceinline__ float lse2_2(float x, float y) {
    float h = fmaxf(x, y), l = fminf(x, y);
    return h + lg2(1.0f + ex2(l - h));
}
__device__ __forceinline__ float lse2_3(float x, float y, float z) {
    float h = fmaxf(x, y), l = fminf(x, y);
    float m = fmaxf(h, z), s = fminf(h, z);
    return m + lg2(1.0f + ex2(s - m) + ex2(l - m));
}

__global__ __launch_bounds__(NTHREADS, 1)
void ctc_alpha_kernel(const float* __restrict__ pred,      // (T,B,A) log-softmax (ln)
                      const int*   __restrict__ target,    // (B,L)
                      const int*   __restrict__ pred_lens,
                      const int*   __restrict__ target_lens,
                      float*       __restrict__ out)
{
    const int b    = blockIdx.x;
    const int tid  = threadIdx.x;
    const int wid  = tid >> 5;
    const int lane = tid & 31;

    __shared__ float rows[2][PF * A_N]; // double-buffered e-rows, log2 domain
    __shared__ float bnd[2][NWARPS];    // double-buffered warp boundaries
    __shared__ float fin[2];

    const float LOG2E   = 1.4426950408889634f;
    const float LN2     = 0.6931471805599453f;
    const float NEG_BIG = -1e30f;
    const float L2_EPS  = -13.287712379549449f;  // log2(0.0001)
    const float L2_HALF = -1.0028901240599430f;  // log2(0.499)

    const int Tb   = pred_lens[b];
    const int TbM1 = Tb - 1;
    const int tl   = target_lens[b];

    // Final-state owners: f0 = alpha[2tl-1] (odd), f1 = alpha[2tl] (even)
    const int  s0 = 2 * tl - 1, s1 = 2 * tl;
    const bool f0_here = (tid == (s0 >> 2));
    const bool f0_isB  = ((s0 >> 1) & 1) != 0;
    const bool f1_here = (tid == (s1 >> 2));
    const bool f1_isB  = ((s1 >> 1) & 1) != 0;

    // Symbols for the two odd states this thread owns (coalesced int2)
    int symA = 0, symB = 0;
    if (tid < L_N / 2) {
        int2 sv = ((const int2*)(target + b * L_N))[tid];
        symA = sv.x; symB = sv.y;
    }

    const size_t stride_t = (size_t)B_N * A_N;
    const float* __restrict__ pred_b = pred + (size_t)b * A_N;

    // Register alphas (log2): pair A = (4t,4t+1), pair B = (4t+2,4t+3)
    float a0 = (tid == 0) ? L2_HALF : L2_EPS;
    float a1 = (tid == 0) ? L2_HALF : L2_EPS;
    float b0 = L2_EPS;
    float b1 = L2_EPS;
    float f0c = L2_EPS, f1c = L2_EPS;

    // t=1 reads bnd[1][...]
    if (tid < NWARPS) bnd[1][tid] = (tid == 0) ? NEG_BIG : L2_EPS;

    const int roff0 = tid >> 5;        // 0..3
    const int roff1 = roff0 + 4;       // 4..7
    rows[0][tid]       = pred_b[(size_t)min(1 + roff0, T_MAX - 1) * stride_t + lane] * LOG2E;
    rows[0][tid + 128] = pred_b[(size_t)min(1 + roff1, T_MAX - 1) * stride_t + lane] * LOG2E;
    float pf0 = pred_b[(size_t)min(9 + roff0, T_MAX - 1) * stride_t + lane];
    float pf1 = pred_b[(size_t)min(9 + roff1, T_MAX - 1) * stride_t + lane];

    // Pre-shuffled neighbor value for the first step (hoisted off the chain)
    float apsh = __shfl_up_sync(0xffffffffu, b1, 1);
    __syncthreads();

    int phase = 0;
    for (int base = 1; base < Tb; base += PF) {
        #pragma unroll
        for (int u = 0; u < PF; ++u) {
            const int t  = base + u;
            const int rb = (1 + u) & 1;       // t parity (base odd)
            const float* __restrict__ rc = &rows[phase][u * A_N];

            const float eb  = rc[0];
            const float esA = rc[symA];
            const float esB = rc[symB];

            // pair A left-neighbor: pre-shuffled last step; lane0 patches from bnd
            float ap = apsh;
            if (lane == 0) ap = (wid == 0) ? NEG_BIG : bnd[rb][wid - 1];

            const float bp = a1;              // pair B left-neighbor (register)

            float na0 = eb  + lse2_2(a0, ap);
            float na1 = esA + lse2_3(a0, ap, a1);
            float nb0 = eb  + lse2_2(b0, bp);
            float nb1 = esB + lse2_3(b0, bp, b1);

            a0 = na0; a1 = na1; b0 = nb0; b1 = nb1;

            // hoist next step's shuffle BEFORE the barrier (b1 is final here)
            apsh = __shfl_up_sync(0xffffffffu, b1, 1);
            if (lane == 31) bnd[rb ^ 1][wid] = b1;

            if (t == TbM1) {
                if (f0_here) f0c = f0_isB ? b1 : a1;
                if (f1_here) f1c = f1_isB ? b0 : a0;
            }

            if (u == PF - 1) {
                rows[phase ^ 1][tid]       = pf0 * LOG2E;
                rows[phase ^ 1][tid + 128] = pf1 * LOG2E;
                pf0 = pred_b[(size_t)min(t + 1 + PF + roff0, T_MAX - 1) * stride_t + lane];
                pf1 = pred_b[(size_t)min(t + 1 + PF + roff1, T_MAX - 1) * stride_t + lane];
                phase ^= 1;
            }
            __syncthreads();
        }
    }

    if (f0_here) fin[0] = f0c;
    if (f1_here) fin[1] = f1c;
    __syncthreads();

    if (tid == 0) {
        d_per_batch[b] = LN2 * lse2_2(fin[0], fin[1]);
        __threadfence();
        unsigned old = atomicAdd(&g_ticket, 1u);
        if (old == B_N - 1) {
            float s = 0.0f;
            #pragma unroll 4
            for (int i = 0; i < B_N; ++i)
                s += __ldcg(&d_per_batch[i]);   // fixed order -> deterministic
            out[0] = -s * (1.0f / (float)B_N);
            g_ticket = 0;                       // reset for next graph replay
        }
    }
}

extern "C" void kernel_launch(void* const* d_in, const int* in_sizes, int n_in,
                              void* d_out, int out_size)
{
    const float* prediction  = (const float*)d_in[0];
    const int*   target      = (const int*)  d_in[1];
    const int*   pred_lens   = (const int*)  d_in[2];
    const int*   target_lens = (const int*)  d_in[3];

    ctc_alpha_kernel<<<B_N, NTHREADS>>>(prediction, target, pred_lens, target_lens,
                                        (float*)d_out);
}

// round 15
// speedup vs baseline: 1.2882x; 1.1077x over previous
#include <cuda_runtime.h>
#include <math.h>

#define T_MAX 2000
#define B_N   64
#define A_N   32
#define L_N   200

#define NTHREADS 128
#define NWARPS   4
#define PF       8         // rows per LDG burst; PF/2 fused iterations per group

__device__ float    d_per_batch[B_N];
__device__ unsigned g_ticket = 0;

__device__ __forceinline__ float ex2(float x) {
    float r; asm("ex2.approx.ftz.f32 %0, %1;" : "=f"(r) : "f"(x)); return r;
}
__device__ __forceinline__ float lg2(float x) {
    float r; asm("lg2.approx.ftz.f32 %0, %1;" : "=f"(r) : "f"(x)); return r;
}
__device__ __forceinline__ float lse2_2(float x, float y) {
    float h = fmaxf(x, y), l = fminf(x, y);
    return h + lg2(1.0f + ex2(l - h));
}

__global__ __launch_bounds__(NTHREADS, 1)
void ctc_alpha_kernel(const float* __restrict__ pred,      // (T,B,A) log-softmax (ln)
                      const int*   __restrict__ target,    // (B,L)
                      const int*   __restrict__ pred_lens,
                      const int*   __restrict__ target_lens,
                      float*       __restrict__ out)
{
    const int b    = blockIdx.x;
    const int tid  = threadIdx.x;
    const int wid  = tid >> 5;
    const int lane = tid & 31;

    __shared__ float rows[2][PF * A_N];    // double-buffered E-rows, LINEAR domain
    __shared__ float bnd[2][NWARPS][4];    // {b1,b0,a1} per warp (log2), double-buffered
    __shared__ float fin[2];

    const float LOG2E   = 1.4426950408889634f;
    const float LN2     = 0.6931471805599453f;
    const float NEG_BIG = -1e30f;
    const float L2_EPS  = -13.287712379549449f;  // log2(0.0001)
    const float L2_HALF = -1.0028901240599430f;  // log2(0.499)

    const int Tb   = pred_lens[b];
    const int TbM1 = Tb - 1;
    const int tl   = target_lens[b];

    // Final-state owners: f0 = alpha[2tl-1] (odd), f1 = alpha[2tl] (even)
    const int  s0 = 2 * tl - 1, s1 = 2 * tl;
    const bool f0_here = (tid == (s0 >> 2));
    const bool f0_isB  = ((s0 >> 1) & 1) != 0;
    const bool f1_here = (tid == (s1 >> 2));
    const bool f1_isB  = ((s1 >> 1) & 1) != 0;

    // Own odd-state symbols (4t+1 -> target[2t], 4t+3 -> target[2t+1])
    int symA = 0, symB = 0;
    if (tid < L_N / 2) {
        int2 sv = ((const int2*)(target + b * L_N))[tid];
        symA = sv.x; symB = sv.y;
    }
    // Halo symbol: state 4t-1 -> target[2t-1]
    int symBL = 0;
    {
        int li = 2 * tid - 1;
        if (li >= 0 && li < L_N) symBL = target[b * L_N + li];
    }

    const size_t stride_t = (size_t)B_N * A_N;
    const float* __restrict__ pred_b = pred + (size_t)b * A_N;

    // Register alphas (log2): pair A = (4t,4t+1), pair B = (4t+2,4t+3)
    float a0 = (tid == 0) ? L2_HALF : L2_EPS;
    float a1 = (tid == 0) ? L2_HALF : L2_EPS;
    float b0 = L2_EPS;
    float b1 = L2_EPS;
    float f0c = L2_EPS, f1c = L2_EPS;

    // First fused iteration reads bnd[0]: t=0 boundary values of warp w-1
    if (tid < NWARPS) {
        bnd[0][tid][0] = L2_EPS;   // b1 (state 128w-1)
        bnd[0][tid][1] = L2_EPS;   // b0
        bnd[0][tid][2] = L2_EPS;   // a1
    }

    const int roff0 = tid >> 5;        // 0..3
    const int roff1 = roff0 + 4;       // 4..7
    rows[0][tid]       = ex2(pred_b[(size_t)min(1 + roff0, T_MAX - 1) * stride_t + lane] * LOG2E);
    rows[0][tid + 128] = ex2(pred_b[(size_t)min(1 + roff1, T_MAX - 1) * stride_t + lane] * LOG2E);
    float pf0 = pred_b[(size_t)min(9 + roff0, T_MAX - 1) * stride_t + lane];
    float pf1 = pred_b[(size_t)min(9 + roff1, T_MAX - 1) * stride_t + lane];

    // Pre-shuffled left-halo values for the first iteration (hoisted off chain)
    float shB1 = __shfl_up_sync(0xffffffffu, b1, 1);
    float shB0 = __shfl_up_sync(0xffffffffu, b0, 1);
    float shA1 = __shfl_up_sync(0xffffffffu, a1, 1);
    __syncthreads();

    int phase = 0;
    for (int base = 1; base < Tb; base += PF) {
        #pragma unroll
        for (int u = 0; u < PF / 2; ++u) {      // each u = 2 time steps
            const int t  = base + 2 * u;
            const int rb = u & 1;
            const float* __restrict__ rc1 = &rows[phase][(2 * u)     * A_N];
            const float* __restrict__ rc2 = &rows[phase][(2 * u + 1) * A_N];

            const float Eb1  = rc1[0];
            const float EsA1 = rc1[symA];
            const float EsB1 = rc1[symB];
            const float EsBL = rc1[symBL];
            const float Eb2  = rc2[0];
            const float EsA2 = rc2[symA];
            const float EsB2 = rc2[symB];

            // Left halo at t-1: states 4i-1, 4i-2, 4i-3 (log2)
            float bL1 = shB1, bL0 = shB0, aL1 = shA1;
            if (lane == 0) {
                if (wid == 0) { bL1 = NEG_BIG; bL0 = NEG_BIG; aL1 = NEG_BIG; }
                else {
                    bL1 = bnd[rb][wid - 1][0];
                    bL0 = bnd[rb][wid - 1][1];
                    aL1 = bnd[rb][wid - 1][2];
                }
            }

            // Local max + guard (m = -inf only if whole window is -inf)
            float m = fmaxf(fmaxf(fmaxf(a0, a1), fmaxf(b0, b1)),
                            fmaxf(fmaxf(bL1, bL0), aL1));
            if (m < -1e37f) m = 0.0f;

            // To linear (7 ex2)
            float A0 = ex2(a0 - m), A1 = ex2(a1 - m);
            float B0 = ex2(b0 - m), B1 = ex2(b1 - m);
            float P1 = ex2(bL1 - m), P0 = ex2(bL0 - m), Q = ex2(aL1 - m);

            // ---- step t (pure FMA) ----
            float sA  = A0 + P1;
            float nA0 = Eb1  * sA;
            float nA1 = EsA1 * (sA + A1);
            float sB  = B0 + A1;
            float nB0 = Eb1  * sB;
            float nB1 = EsB1 * (sB + B1);
            float nH  = EsBL * (P1 + P0 + Q);     // halo: alpha_t[4i-1]

            if (t == TbM1) {
                if (f0_here) f0c = lg2(f0_isB ? nB1 : nA1) + m;
                if (f1_here) f1c = lg2(f1_isB ? nB0 : nA0) + m;
            }

            // ---- step t+1 (pure FMA) ----
            float tA  = nA0 + nH;
            float mA0 = Eb2  * tA;
            float mA1 = EsA2 * (tA + nA1);
            float tB  = nB0 + nA1;
            float mB0 = Eb2  * tB;
            float mB1 = EsB2 * (tB + nB1);

            // Back to log2 (4 lg2)
            a0 = lg2(mA0) + m;
            a1 = lg2(mA1) + m;
            b0 = lg2(mB0) + m;
            b1 = lg2(mB1) + m;

            if (t + 1 == TbM1) {
                if (f0_here) f0c = f0_isB ? b1 : a1;
                if (f1_here) f1c = f1_isB ? b0 : a0;
            }

            if (lane == 31) {
                bnd[rb ^ 1][wid][0] = b1;
                bnd[rb ^ 1][wid][1] = b0;
                bnd[rb ^ 1][wid][2] = a1;
            }
            // Hoist next iteration's shuffles before the barrier
            shB1 = __shfl_up_sync(0xffffffffu, b1, 1);
            shB0 = __shfl_up_sync(0xffffffffu, b0, 1);
            shA1 = __shfl_up_sync(0xffffffffu, a1, 1);

            if (u == PF / 2 - 1) {
                rows[phase ^ 1][tid]       = ex2(pf0 * LOG2E);
                rows[phase ^ 1][tid + 128] = ex2(pf1 * LOG2E);
                pf0 = pred_b[(size_t)min(t + 2 + PF + roff0, T_MAX - 1) * stride_t + lane];
                pf1 = pred_b[(size_t)min(t + 2 + PF + roff1, T_MAX - 1) * stride_t + lane];
                phase ^= 1;
            }
            __syncthreads();
        }
    }

    if (f0_here) fin[0] = f0c;
    if (f1_here) fin[1] = f1c;
    __syncthreads();

    if (tid == 0) {
        d_per_batch[b] = LN2 * lse2_2(fin[0], fin[1]);
        __threadfence();
        unsigned old = atomicAdd(&g_ticket, 1u);
        if (old == B_N - 1) {
            float s = 0.0f;
            #pragma unroll 4
            for (int i = 0; i < B_N; ++i)
                s += __ldcg(&d_per_batch[i]);   // fixed order -> deterministic
            out[0] = -s * (1.0f / (float)B_N);
            g_ticket = 0;                       // reset for next graph replay
        }
    }
}

extern "C" void kernel_launch(void* const* d_in, const int* in_sizes, int n_in,
                              void* d_out, int out_size)
{
    const float* prediction  = (const float*)d_in[0];
    const int*   target      = (const int*)  d_in[1];
    const int*   pred_lens   = (const int*)  d_in[2];
    const int*   target_lens = (const int*)  d_in[3];

    ctc_alpha_kernel<<<B_N, NTHREADS>>>(prediction, target, pred_lens, target_lens,
                                        (float*)d_out);
}